// round 12
// baseline (speedup 1.0000x reference)
#include <cuda_runtime.h>
#include <cuda_fp16.h>

#define NN   50000
#define NE   800000
#define CDIM 256
#define NPB  8
#define CAPN 96
#define TROW 80

// ---------------- scratch ----------------
__device__ int    g_deg[NN];        // zeroed by k_scanA each call (static-zero 1st call)
__device__ int    g_off[NN + 1];    // block-LOCAL prefix; consumers add spart[n>>12]
__device__ int    g_part[16];
__device__ int    g_cur[NN];
__device__ int2   g_se[NE];         // packed (src, edge-id)
__device__ __half g_gh[(size_t)NN * CDIM];
__device__ float  g_as[NN * 4];
__device__ float  g_ad[NN * 4];
__device__ float  g_outg[(size_t)NN * CDIM];

// ---------------- f32x2 helpers ----------------
__device__ __forceinline__ unsigned long long pack2(float lo, float hi) {
    unsigned long long r;
    asm("mov.b64 %0, {%1, %2};" : "=l"(r) : "f"(lo), "f"(hi));
    return r;
}
__device__ __forceinline__ void fma2(unsigned long long& acc, unsigned long long a,
                                     unsigned long long b) {
    asm("fma.rn.f32x2 %0, %1, %2, %0;" : "+l"(acc) : "l"(a), "l"(b));
}
__device__ __forceinline__ float2 unpack2(unsigned long long v) {
    float2 f;
    asm("mov.b64 {%0, %1}, %2;" : "=f"(f.x), "=f"(f.y) : "l"(v));
    return f;
}

__device__ __forceinline__ float leaky(float v) { return v > 0.f ? v : 0.2f * v; }

// ---------------- degree histogram, 4 edges/thread ----------------
__global__ void k_hist(const int* __restrict__ ei) {
    int t = blockIdx.x * blockDim.x + threadIdx.x;
    int e0 = t * 4;
    if (e0 >= NE) return;
    int4 d = *(const int4*)(ei + NE + e0);
    atomicAdd(&g_deg[d.x], 1);
    atomicAdd(&g_deg[d.y], 1);
    atomicAdd(&g_deg[d.z], 1);
    atomicAdd(&g_deg[d.w], 1);
}

// ---------------- scanA: block-local prefix -> g_off & g_cur; re-zero g_deg ----------------
__global__ void k_scanA() {
    __shared__ int sh[256];
    int t = threadIdx.x, b = blockIdx.x;
    int base = (b * 256 + t) * 16;
    int local[16];
    int s = 0;
#pragma unroll
    for (int i = 0; i < 16; i++) {
        int idx = base + i;
        int v = (idx < NN) ? g_deg[idx] : 0;
        local[i] = v; s += v;
    }
    sh[t] = s;
    __syncthreads();
    for (int ofs = 1; ofs < 256; ofs <<= 1) {
        int v = (t >= ofs) ? sh[t - ofs] : 0;
        __syncthreads();
        sh[t] += v;
        __syncthreads();
    }
    int excl = sh[t] - s;
    if (t == 255) g_part[b] = sh[255];
    int run = excl;
#pragma unroll
    for (int i = 0; i < 16; i++) {
        int idx = base + i;
        if (idx < NN) { g_off[idx] = run; g_cur[idx] = run; g_deg[idx] = 0; }
        run += local[i];
    }
}

// ---------------- CSR scatter, 4 edges/thread; adds block partials inline ----------------
__global__ void k_scatter(const int* __restrict__ ei) {
    __shared__ int spart[13];
    int tid = threadIdx.x;
    if (tid < 13) {
        int s = 0;
        for (int b = 0; b < tid; b++) s += g_part[b];
        spart[tid] = s;
    }
    __syncthreads();
    int t = blockIdx.x * blockDim.x + tid;
    int e0 = t * 4;
    if (e0 >= NE) return;
    int4 s4 = *(const int4*)(ei + e0);
    int4 d4 = *(const int4*)(ei + NE + e0);
    int p0 = atomicAdd(&g_cur[d4.x], 1) + spart[d4.x >> 12];
    int p1 = atomicAdd(&g_cur[d4.y], 1) + spart[d4.y >> 12];
    int p2 = atomicAdd(&g_cur[d4.z], 1) + spart[d4.z >> 12];
    int p3 = atomicAdd(&g_cur[d4.w], 1) + spart[d4.w >> 12];
    g_se[p0] = make_int2(s4.x, e0);
    g_se[p1] = make_int2(s4.y, e0 + 1);
    g_se[p2] = make_int2(s4.z, e0 + 2);
    g_se[p3] = make_int2(s4.w, e0 + 3);
}

// ---------------- fused: shuffle-free T-gather + h + g(->fp16) + att logits ----------------
__global__ void k_g(const float* __restrict__ x, const float* __restrict__ ea,
                    const float* __restrict__ root, const float* __restrict__ ebias,
                    const float* __restrict__ lin, const float* __restrict__ atts,
                    const float* __restrict__ attd, const float* __restrict__ mlpw,
                    const float* __restrict__ mlpb) {
    __shared__ float slin[16 * CDIM];
    __shared__ float shh[16 * 16];
    __shared__ float sred[16][8];
    __shared__ float sT[16 * TROW];
    __shared__ float sW2[72 * 16];
    __shared__ int   spart[13];
    int tid = threadIdx.x, lane = tid & 31, warp = tid >> 5;
    int n0 = blockIdx.x * 16;
    for (int i = tid; i < 16 * CDIM; i += 256) slin[i] = lin[i];
    for (int idx = tid; idx < 1024; idx += 256) {
        int f = idx >> 7, rest = idx & 127, i = rest >> 4, o = rest & 15;
        sW2[(f * 8 + i) * 16 + o] = mlpw[idx];
    }
    if (tid < 128) sW2[(64 + (tid >> 4)) * 16 + (tid & 15)] = mlpb[tid];
    if (tid < 13) {
        int s = 0;
        for (int b = 0; b < tid; b++) s += g_part[b];
        spart[tid] = s;
    }
    __syncthreads();

    // T-gather: warp handles nodes m = warp, warp+8; NO shuffles — every lane
    // fetches its own operands (se: broadcast LDG; ea: 32B sector; x: 32B sector).
    for (int m = warp; m < 16; m += 8) {
        int n = n0 + m;
        if (n >= NN) break;
        int o0 = 0, o1 = 0;
        if (lane == 0) {
            o0 = g_off[n] + spart[n >> 12];
            o1 = (n + 1 == NN) ? NE : g_off[n + 1] + spart[(n + 1) >> 12];
        }
        int beg = __shfl_sync(0xffffffffu, o0, 0);
        int deg = __shfl_sync(0xffffffffu, o1, 0) - beg;
        int f_own = lane >> 2, iA = (lane & 3) * 2;
        float T0 = 0.f, T1 = 0.f, S0 = 0.f, S1 = 0.f;
        const int2* sep = g_se + beg;
        int j = 0;
        for (; j + 4 <= deg; j += 4) {
            int2 se0 = sep[j];
            int2 se1 = sep[j + 1];
            int2 se2 = sep[j + 2];
            int2 se3 = sep[j + 3];
            float a0 = ea[(size_t)se0.y * 8 + f_own];
            float a1 = ea[(size_t)se1.y * 8 + f_own];
            float a2 = ea[(size_t)se2.y * 8 + f_own];
            float a3 = ea[(size_t)se3.y * 8 + f_own];
            float2 x0 = *(const float2*)(x + (size_t)se0.x * 8 + iA);
            float2 x1 = *(const float2*)(x + (size_t)se1.x * 8 + iA);
            float2 x2 = *(const float2*)(x + (size_t)se2.x * 8 + iA);
            float2 x3 = *(const float2*)(x + (size_t)se3.x * 8 + iA);
            T0 += a0 * x0.x; T1 += a0 * x0.y;
            T0 += a1 * x1.x; T1 += a1 * x1.y;
            T0 += a2 * x2.x; T1 += a2 * x2.y;
            T0 += a3 * x3.x; T1 += a3 * x3.y;
            if (f_own == 0) {
                S0 += x0.x + x1.x + x2.x + x3.x;
                S1 += x0.y + x1.y + x2.y + x3.y;
            }
        }
        for (; j < deg; j++) {
            int2 se = sep[j];
            float a = ea[(size_t)se.y * 8 + f_own];
            float2 xv = *(const float2*)(x + (size_t)se.x * 8 + iA);
            T0 += a * xv.x; T1 += a * xv.y;
            if (f_own == 0) { S0 += xv.x; S1 += xv.y; }
        }
        float* tr = sT + m * TROW;
        *(float2*)(tr + f_own * 8 + iA) = make_float2(T0, T1);
        if (f_own == 0) *(float2*)(tr + 64 + iA) = make_float2(S0, S1);
    }
    __syncthreads();

    // h stage
    {
        int m = tid >> 4, k = tid & 15;
        int n = n0 + m;
        float v = 0.f;
        if (n < NN) {
            v = ebias[k];
            const float* tr = sT + m * TROW;
#pragma unroll 8
            for (int j = 0; j < 72; j++) v += tr[j] * sW2[j * 16 + k];
            const float* xr = x + (size_t)n * 8;
#pragma unroll
            for (int i = 0; i < 8; i++) v += xr[i] * root[i * 16 + k];
            v = fmaxf(v, 0.f);
        }
        shh[tid] = v;
    }
    __syncthreads();
    float acc[16];
#pragma unroll
    for (int m = 0; m < 16; m++) acc[m] = 0.f;
#pragma unroll
    for (int k = 0; k < 16; k++) {
        float w = slin[k * CDIM + tid];
#pragma unroll
        for (int m = 0; m < 16; m++) acc[m] += shh[m * 16 + k] * w;
    }
#pragma unroll
    for (int m = 0; m < 16; m++) {
        int n = n0 + m;
        if (n < NN) g_gh[(size_t)n * CDIM + tid] = __float2half(acc[m]);
    }
    float a_s = atts[tid], a_d = attd[tid];
#pragma unroll
    for (int m = 0; m < 16; m++) {
        float s = acc[m] * a_s;
#pragma unroll
        for (int o = 16; o; o >>= 1) s += __shfl_xor_sync(0xffffffffu, s, o);
        if (lane == 0) sred[m][warp] = s;
    }
    __syncthreads();
    if (tid < 64) {
        int m = tid >> 2, h = tid & 3;
        int n = n0 + m;
        if (n < NN) g_as[n * 4 + h] = sred[m][2 * h] + sred[m][2 * h + 1];
    }
    __syncthreads();
#pragma unroll
    for (int m = 0; m < 16; m++) {
        float s = acc[m] * a_d;
#pragma unroll
        for (int o = 16; o; o >>= 1) s += __shfl_xor_sync(0xffffffffu, s, o);
        if (lane == 0) sred[m][warp] = s;
    }
    __syncthreads();
    if (tid < 64) {
        int m = tid >> 2, h = tid & 3;
        int n = n0 + m;
        if (n < NN) g_ad[n * 4 + h] = sred[m][2 * h] + sred[m][2 * h + 1];
    }
}

// ---------------- GAT: warp-per-node ----------------
__global__ void k_gatagg(const float* __restrict__ gbias) {
    __shared__ int   s_src[NPB][CAPN];
    __shared__ float s_e[NPB][CAPN][4];
    __shared__ int   spart[13];
    int tid = threadIdx.x, lane = tid & 31, w = tid >> 5;
    if (tid < 13) {
        int s = 0;
        for (int b = 0; b < tid; b++) s += g_part[b];
        spart[tid] = s;
    }
    __syncthreads();
    int n = blockIdx.x * NPB + w;
    if (n >= NN) return;
    int beg = g_off[n] + spart[n >> 12];
    int end = (n + 1 == NN) ? NE : g_off[n + 1] + spart[(n + 1) >> 12];
    int deg = end - beg;
    int c8 = lane * 8, h = lane >> 3;

    // ---- phase 1: unnormalized exp weights + per-head sums ----
    float4 adv = *(const float4*)(g_ad + n * 4);
    float ad[4] = {adv.x, adv.y, adv.z, adv.w};
    float ls[4] = {0.f, 0.f, 0.f, 0.f};
    if (deg <= CAPN) {
        for (int j = lane; j < deg; j += 32) {
            int s = g_se[beg + j].x;
            s_src[w][j] = s;
            float4 av = *(const float4*)(g_as + s * 4);
            float e0 = __expf(leaky(av.x + ad[0]));
            float e1 = __expf(leaky(av.y + ad[1]));
            float e2 = __expf(leaky(av.z + ad[2]));
            float e3 = __expf(leaky(av.w + ad[3]));
            *(float4*)&s_e[w][j][0] = make_float4(e0, e1, e2, e3);
            ls[0] += e0; ls[1] += e1; ls[2] += e2; ls[3] += e3;
        }
    } else {
        for (int j = lane; j < deg; j += 32) {
            int s = g_se[beg + j].x;
            float4 av = *(const float4*)(g_as + s * 4);
            ls[0] += __expf(leaky(av.x + ad[0]));
            ls[1] += __expf(leaky(av.y + ad[1]));
            ls[2] += __expf(leaky(av.z + ad[2]));
            ls[3] += __expf(leaky(av.w + ad[3]));
        }
    }
#pragma unroll
    for (int o = 16; o; o >>= 1)
#pragma unroll
        for (int k = 0; k < 4; k++)
            ls[k] += __shfl_xor_sync(0xffffffffu, ls[k], o);
    float inv = 1.f / (ls[h] + 1e-16f);
    __syncwarp();

    // ---- phase 2: aggregation; lane owns channels c8..c8+7 ----
    float a0 = 0.f, a1 = 0.f, a2 = 0.f, a3 = 0.f;
    float a4 = 0.f, a5 = 0.f, a6 = 0.f, a7 = 0.f;
    if (deg <= CAPN) {
#pragma unroll 8
        for (int j = 0; j < deg; j++) {
            float e = s_e[w][j][h];
            uint4 raw = *(const uint4*)(g_gh + ((size_t)s_src[w][j] << 8) + c8);
            float2 g0 = __half22float2(*(__half2*)&raw.x);
            float2 g1 = __half22float2(*(__half2*)&raw.y);
            float2 g2 = __half22float2(*(__half2*)&raw.z);
            float2 g3 = __half22float2(*(__half2*)&raw.w);
            a0 += e * g0.x; a1 += e * g0.y;
            a2 += e * g1.x; a3 += e * g1.y;
            a4 += e * g2.x; a5 += e * g2.y;
            a6 += e * g3.x; a7 += e * g3.y;
        }
    } else {
        float adh = ad[h];
        for (int j = 0; j < deg; j++) {
            int s = g_se[beg + j].x;
            float e = __expf(leaky(g_as[s * 4 + h] + adh));
            uint4 raw = *(const uint4*)(g_gh + ((size_t)s << 8) + c8);
            float2 g0 = __half22float2(*(__half2*)&raw.x);
            float2 g1 = __half22float2(*(__half2*)&raw.y);
            float2 g2 = __half22float2(*(__half2*)&raw.z);
            float2 g3 = __half22float2(*(__half2*)&raw.w);
            a0 += e * g0.x; a1 += e * g0.y;
            a2 += e * g1.x; a3 += e * g1.y;
            a4 += e * g2.x; a5 += e * g2.y;
            a6 += e * g3.x; a7 += e * g3.y;
        }
    }
    float4 b0 = *(const float4*)(gbias + c8);
    float4 b1 = *(const float4*)(gbias + c8 + 4);
    float* outp = g_outg + (size_t)n * CDIM + c8;
    *(float4*)outp = make_float4(
        fmaxf(a0 * inv + b0.x, 0.f), fmaxf(a1 * inv + b0.y, 0.f),
        fmaxf(a2 * inv + b0.z, 0.f), fmaxf(a3 * inv + b0.w, 0.f));
    *(float4*)(outp + 4) = make_float4(
        fmaxf(a4 * inv + b1.x, 0.f), fmaxf(a5 * inv + b1.y, 0.f),
        fmaxf(a6 * inv + b1.z, 0.f), fmaxf(a7 * inv + b1.w, 0.f));
}

// ---------------- final linear via f32x2 (k-step-2) ----------------
__global__ void k_fc(const float* __restrict__ w, const float* __restrict__ b,
                     float* __restrict__ out) {
    __shared__ float sxP[16 * 512];
    int tid = threadIdx.x;
    int n0 = blockIdx.x * 32;
    for (int i = tid; i < 2048; i += 128) {
        int m0 = i >> 7, kq = i & 127;
        int na = n0 + m0, nb = na + 16;
        float2 a = (na < NN) ? *(const float2*)(g_outg + (size_t)na * 256 + kq * 2)
                             : make_float2(0.f, 0.f);
        float2 c = (nb < NN) ? *(const float2*)(g_outg + (size_t)nb * 256 + kq * 2)
                             : make_float2(0.f, 0.f);
        *(float4*)(sxP + m0 * 512 + kq * 4) = make_float4(a.x, c.x, a.y, c.y);
    }
    __syncthreads();
    int o = tid;
    unsigned long long acc[16];
#pragma unroll
    for (int m = 0; m < 16; m++) acc[m] = 0ULL;
#pragma unroll 2
    for (int k = 0; k < 256; k += 2) {
        float w0 = w[k * 128 + o];
        float w1 = w[(k + 1) * 128 + o];
        unsigned long long wd0 = pack2(w0, w0);
        unsigned long long wd1 = pack2(w1, w1);
#pragma unroll
        for (int m = 0; m < 16; m++) {
            ulonglong2 xv = *(const ulonglong2*)(sxP + m * 512 + k * 2);
            fma2(acc[m], xv.x, wd0);
            fma2(acc[m], xv.y, wd1);
        }
    }
    float bias = b[o];
#pragma unroll
    for (int m = 0; m < 16; m++) {
        float2 r = unpack2(acc[m]);
        int na = n0 + m, nb = na + 16;
        if (na < NN) out[(size_t)na * 128 + o] = r.x + bias;
        if (nb < NN) out[(size_t)nb * 128 + o] = r.y + bias;
    }
}

// ---------------- launcher ----------------
extern "C" void kernel_launch(void* const* d_in, const int* in_sizes, int n_in,
                              void* d_out, int out_size) {
    const float* x        = (const float*)d_in[0];
    const int*   ei       = (const int*)d_in[1];
    const float* ea       = (const float*)d_in[2];
    const float* ecc_root = (const float*)d_in[3];
    const float* ecc_bias = (const float*)d_in[4];
    const float* mlp_w    = (const float*)d_in[5];
    const float* mlp_b    = (const float*)d_in[6];
    const float* gat_lin  = (const float*)d_in[7];
    const float* att_src  = (const float*)d_in[8];
    const float* att_dst  = (const float*)d_in[9];
    const float* gat_bias = (const float*)d_in[10];
    const float* fc_w     = (const float*)d_in[11];
    const float* fc_b     = (const float*)d_in[12];
    float*       out      = (float*)d_out;

    k_hist<<<(NE / 4 + 255) / 256, 256>>>(ei);              // 0
    k_scanA<<<13, 256>>>();                                 // 1
    k_scatter<<<(NE / 4 + 255) / 256, 256>>>(ei);           // 2
    k_g<<<(NN + 15) / 16, 256>>>(x, ea, ecc_root, ecc_bias, gat_lin,
                                 att_src, att_dst, mlp_w, mlp_b); // 3 <- profiled
    k_gatagg<<<(NN + NPB - 1) / NPB, 256>>>(gat_bias);      // 4
    k_fc<<<(NN + 31) / 32, 128>>>(fc_w, fc_b, out);         // 5
}

// round 14
// speedup vs baseline: 1.0496x; 1.0496x over previous
#include <cuda_runtime.h>
#include <cuda_fp16.h>

#define NN   50000
#define NE   800000
#define CDIM 256
#define NPB  8
#define CAPN 96
#define TROW 80

// ---------------- scratch ----------------
__device__ int    g_deg[NN];        // zeroed by k_scanA each call (static-zero 1st call)
__device__ int    g_off[NN + 1];    // block-LOCAL prefix; consumers add spart[n>>12]
__device__ int    g_part[16];
__device__ int    g_cur[NN];
__device__ int2   g_se[NE];         // packed (src, edge-id)
__device__ __half g_gh[(size_t)NN * CDIM];
__device__ float  g_as[NN * 4];
__device__ float  g_ad[NN * 4];
__device__ float  g_outg[(size_t)NN * CDIM];

// ---------------- f32x2 helpers ----------------
__device__ __forceinline__ unsigned long long pack2(float lo, float hi) {
    unsigned long long r;
    asm("mov.b64 %0, {%1, %2};" : "=l"(r) : "f"(lo), "f"(hi));
    return r;
}
__device__ __forceinline__ void fma2(unsigned long long& acc, unsigned long long a,
                                     unsigned long long b) {
    asm("fma.rn.f32x2 %0, %1, %2, %0;" : "+l"(acc) : "l"(a), "l"(b));
}
__device__ __forceinline__ float2 unpack2(unsigned long long v) {
    float2 f;
    asm("mov.b64 {%0, %1}, %2;" : "=f"(f.x), "=f"(f.y) : "l"(v));
    return f;
}

__device__ __forceinline__ float leaky(float v) { return v > 0.f ? v : 0.2f * v; }

// ---------------- degree histogram, 4 edges/thread ----------------
__global__ void k_hist(const int* __restrict__ ei) {
    int t = blockIdx.x * blockDim.x + threadIdx.x;
    int e0 = t * 4;
    if (e0 >= NE) return;
    int4 d = *(const int4*)(ei + NE + e0);
    atomicAdd(&g_deg[d.x], 1);
    atomicAdd(&g_deg[d.y], 1);
    atomicAdd(&g_deg[d.z], 1);
    atomicAdd(&g_deg[d.w], 1);
}

// ---------------- scanA: block-local prefix -> g_off & g_cur; re-zero g_deg ----------------
__global__ void k_scanA() {
    __shared__ int sh[256];
    int t = threadIdx.x, b = blockIdx.x;
    int base = (b * 256 + t) * 16;
    int local[16];
    int s = 0;
#pragma unroll
    for (int i = 0; i < 16; i++) {
        int idx = base + i;
        int v = (idx < NN) ? g_deg[idx] : 0;
        local[i] = v; s += v;
    }
    sh[t] = s;
    __syncthreads();
    for (int ofs = 1; ofs < 256; ofs <<= 1) {
        int v = (t >= ofs) ? sh[t - ofs] : 0;
        __syncthreads();
        sh[t] += v;
        __syncthreads();
    }
    int excl = sh[t] - s;
    if (t == 255) g_part[b] = sh[255];
    int run = excl;
#pragma unroll
    for (int i = 0; i < 16; i++) {
        int idx = base + i;
        if (idx < NN) { g_off[idx] = run; g_cur[idx] = run; g_deg[idx] = 0; }
        run += local[i];
    }
}

// ---------------- CSR scatter, 4 edges/thread; adds block partials inline ----------------
__global__ void k_scatter(const int* __restrict__ ei) {
    __shared__ int spart[13];
    int tid = threadIdx.x;
    if (tid < 13) {
        int s = 0;
        for (int b = 0; b < tid; b++) s += g_part[b];
        spart[tid] = s;
    }
    __syncthreads();
    int t = blockIdx.x * blockDim.x + tid;
    int e0 = t * 4;
    if (e0 >= NE) return;
    int4 s4 = *(const int4*)(ei + e0);
    int4 d4 = *(const int4*)(ei + NE + e0);
    int p0 = atomicAdd(&g_cur[d4.x], 1) + spart[d4.x >> 12];
    int p1 = atomicAdd(&g_cur[d4.y], 1) + spart[d4.y >> 12];
    int p2 = atomicAdd(&g_cur[d4.z], 1) + spart[d4.z >> 12];
    int p3 = atomicAdd(&g_cur[d4.w], 1) + spart[d4.w >> 12];
    g_se[p0] = make_int2(s4.x, e0);
    g_se[p1] = make_int2(s4.y, e0 + 1);
    g_se[p2] = make_int2(s4.z, e0 + 2);
    g_se[p3] = make_int2(s4.w, e0 + 3);
}

// ---------------- fused: T-gather(8 edges/iter) + h + g(->fp16) + att logits ----------------
__global__ void __launch_bounds__(256, 5)
k_g(const float* __restrict__ x, const float* __restrict__ ea,
    const float* __restrict__ root, const float* __restrict__ ebias,
    const float* __restrict__ lin, const float* __restrict__ atts,
    const float* __restrict__ attd, const float* __restrict__ mlpw,
    const float* __restrict__ mlpb) {
    __shared__ float slin[16 * CDIM];
    __shared__ float shh[16 * 16];
    __shared__ float sred[16][8];
    __shared__ float sT[16 * TROW];
    __shared__ float sW2[72 * 16];
    __shared__ int   spart[13];
    int tid = threadIdx.x, lane = tid & 31, warp = tid >> 5;
    int n0 = blockIdx.x * 16;
    for (int i = tid; i < 16 * CDIM; i += 256) slin[i] = lin[i];
    for (int idx = tid; idx < 1024; idx += 256) {
        int f = idx >> 7, rest = idx & 127, i = rest >> 4, o = rest & 15;
        sW2[(f * 8 + i) * 16 + o] = mlpw[idx];
    }
    if (tid < 128) sW2[(64 + (tid >> 4)) * 16 + (tid & 15)] = mlpb[tid];
    if (tid < 13) {
        int s = 0;
        for (int b = 0; b < tid; b++) s += g_part[b];
        spart[tid] = s;
    }
    __syncthreads();

    // T-gather: warp handles nodes m = warp, warp+8; 8 edges per iteration
    for (int m = warp; m < 16; m += 8) {
        int n = n0 + m;
        if (n >= NN) break;
        int beg = 0, deg = 0;
        if (lane == 0) {
            int o0 = g_off[n] + spart[n >> 12];
            int o1 = (n + 1 == NN) ? NE : g_off[n + 1] + spart[(n + 1) >> 12];
            beg = o0; deg = o1 - o0;
        }
        beg = __shfl_sync(0xffffffffu, beg, 0);
        deg = __shfl_sync(0xffffffffu, deg, 0);
        int f_own = lane >> 2, iA = (lane & 3) * 2;
        float T0 = 0.f, T1 = 0.f, S0 = 0.f, S1 = 0.f;
        int c = lane & 7;
        int el0 = lane >> 3, el1 = 4 + el0;
        for (int jb = 0; jb < deg; jb += 8) {
            int sidx = 0, eidx = 0;
            if (lane < 8 && jb + lane < deg) {
                int2 se = g_se[beg + jb + lane];
                sidx = se.x; eidx = se.y;
            }
            int sj0 = __shfl_sync(0xffffffffu, sidx, el0);
            int ej0 = __shfl_sync(0xffffffffu, eidx, el0);
            int sj1 = __shfl_sync(0xffffffffu, sidx, el1);
            int ej1 = __shfl_sync(0xffffffffu, eidx, el1);
            float av0 = 0.f, xv0 = 0.f, av1 = 0.f, xv1 = 0.f;
            if (jb + el0 < deg) {
                av0 = ea[(size_t)ej0 * 8 + c];
                xv0 = x[(size_t)sj0 * 8 + c];
            }
            if (jb + el1 < deg) {
                av1 = ea[(size_t)ej1 * 8 + c];
                xv1 = x[(size_t)sj1 * 8 + c];
            }
#pragma unroll
            for (int e = 0; e < 4; e++) {
                float eaf = __shfl_sync(0xffffffffu, av0, e * 8 + f_own);
                float xi0 = __shfl_sync(0xffffffffu, xv0, e * 8 + iA);
                float xi1 = __shfl_sync(0xffffffffu, xv0, e * 8 + iA + 1);
                T0 += eaf * xi0;
                T1 += eaf * xi1;
                if (f_own == 0) { S0 += xi0; S1 += xi1; }
            }
#pragma unroll
            for (int e = 0; e < 4; e++) {
                float eaf = __shfl_sync(0xffffffffu, av1, e * 8 + f_own);
                float xi0 = __shfl_sync(0xffffffffu, xv1, e * 8 + iA);
                float xi1 = __shfl_sync(0xffffffffu, xv1, e * 8 + iA + 1);
                T0 += eaf * xi0;
                T1 += eaf * xi1;
                if (f_own == 0) { S0 += xi0; S1 += xi1; }
            }
        }
        float* tr = sT + m * TROW;
        *(float2*)(tr + f_own * 8 + iA) = make_float2(T0, T1);
        if (f_own == 0) *(float2*)(tr + 64 + iA) = make_float2(S0, S1);
    }
    __syncthreads();

    // h stage
    {
        int m = tid >> 4, k = tid & 15;
        int n = n0 + m;
        float v = 0.f;
        if (n < NN) {
            v = ebias[k];
            const float* tr = sT + m * TROW;
#pragma unroll 8
            for (int j = 0; j < 72; j++) v += tr[j] * sW2[j * 16 + k];
            const float* xr = x + (size_t)n * 8;
#pragma unroll
            for (int i = 0; i < 8; i++) v += xr[i] * root[i * 16 + k];
            v = fmaxf(v, 0.f);
        }
        shh[tid] = v;
    }
    __syncthreads();
    float acc[16];
#pragma unroll
    for (int m = 0; m < 16; m++) acc[m] = 0.f;
#pragma unroll
    for (int k = 0; k < 16; k++) {
        float w = slin[k * CDIM + tid];
#pragma unroll
        for (int m = 0; m < 16; m++) acc[m] += shh[m * 16 + k] * w;
    }
#pragma unroll
    for (int m = 0; m < 16; m++) {
        int n = n0 + m;
        if (n < NN) g_gh[(size_t)n * CDIM + tid] = __float2half(acc[m]);
    }
    float a_s = atts[tid], a_d = attd[tid];
#pragma unroll
    for (int m = 0; m < 16; m++) {
        float s = acc[m] * a_s;
#pragma unroll
        for (int o = 16; o; o >>= 1) s += __shfl_xor_sync(0xffffffffu, s, o);
        if (lane == 0) sred[m][warp] = s;
    }
    __syncthreads();
    if (tid < 64) {
        int m = tid >> 2, h = tid & 3;
        int n = n0 + m;
        if (n < NN) g_as[n * 4 + h] = sred[m][2 * h] + sred[m][2 * h + 1];
    }
    __syncthreads();
#pragma unroll
    for (int m = 0; m < 16; m++) {
        float s = acc[m] * a_d;
#pragma unroll
        for (int o = 16; o; o >>= 1) s += __shfl_xor_sync(0xffffffffu, s, o);
        if (lane == 0) sred[m][warp] = s;
    }
    __syncthreads();
    if (tid < 64) {
        int m = tid >> 2, h = tid & 3;
        int n = n0 + m;
        if (n < NN) g_ad[n * 4 + h] = sred[m][2 * h] + sred[m][2 * h + 1];
    }
}

// ---------------- GAT: warp-per-node ----------------
__global__ void __launch_bounds__(256, 6)
k_gatagg(const float* __restrict__ gbias) {
    __shared__ int   s_src[NPB][CAPN];
    __shared__ float s_e[NPB][CAPN][4];
    __shared__ int   spart[13];
    int tid = threadIdx.x, lane = tid & 31, w = tid >> 5;
    if (tid < 13) {
        int s = 0;
        for (int b = 0; b < tid; b++) s += g_part[b];
        spart[tid] = s;
    }
    __syncthreads();
    int n = blockIdx.x * NPB + w;
    if (n >= NN) return;
    int beg = g_off[n] + spart[n >> 12];
    int end = (n + 1 == NN) ? NE : g_off[n + 1] + spart[(n + 1) >> 12];
    int deg = end - beg;
    int c8 = lane * 8, h = lane >> 3;

    // ---- phase 1: unnormalized exp weights + per-head sums ----
    float4 adv = *(const float4*)(g_ad + n * 4);
    float ad[4] = {adv.x, adv.y, adv.z, adv.w};
    float ls[4] = {0.f, 0.f, 0.f, 0.f};
    if (deg <= CAPN) {
        for (int j = lane; j < deg; j += 32) {
            int s = g_se[beg + j].x;
            s_src[w][j] = s;
            float4 av = *(const float4*)(g_as + s * 4);
            float e0 = __expf(leaky(av.x + ad[0]));
            float e1 = __expf(leaky(av.y + ad[1]));
            float e2 = __expf(leaky(av.z + ad[2]));
            float e3 = __expf(leaky(av.w + ad[3]));
            *(float4*)&s_e[w][j][0] = make_float4(e0, e1, e2, e3);
            ls[0] += e0; ls[1] += e1; ls[2] += e2; ls[3] += e3;
        }
    } else {
        for (int j = lane; j < deg; j += 32) {
            int s = g_se[beg + j].x;
            float4 av = *(const float4*)(g_as + s * 4);
            ls[0] += __expf(leaky(av.x + ad[0]));
            ls[1] += __expf(leaky(av.y + ad[1]));
            ls[2] += __expf(leaky(av.z + ad[2]));
            ls[3] += __expf(leaky(av.w + ad[3]));
        }
    }
#pragma unroll
    for (int o = 16; o; o >>= 1)
#pragma unroll
        for (int k = 0; k < 4; k++)
            ls[k] += __shfl_xor_sync(0xffffffffu, ls[k], o);
    float inv = 1.f / (ls[h] + 1e-16f);
    __syncwarp();

    // ---- phase 2: aggregation; lane owns channels c8..c8+7 ----
    float a0 = 0.f, a1 = 0.f, a2 = 0.f, a3 = 0.f;
    float a4 = 0.f, a5 = 0.f, a6 = 0.f, a7 = 0.f;
    if (deg <= CAPN) {
#pragma unroll 8
        for (int j = 0; j < deg; j++) {
            float e = s_e[w][j][h];
            uint4 raw = *(const uint4*)(g_gh + ((size_t)s_src[w][j] << 8) + c8);
            float2 g0 = __half22float2(*(__half2*)&raw.x);
            float2 g1 = __half22float2(*(__half2*)&raw.y);
            float2 g2 = __half22float2(*(__half2*)&raw.z);
            float2 g3 = __half22float2(*(__half2*)&raw.w);
            a0 += e * g0.x; a1 += e * g0.y;
            a2 += e * g1.x; a3 += e * g1.y;
            a4 += e * g2.x; a5 += e * g2.y;
            a6 += e * g3.x; a7 += e * g3.y;
        }
    } else {
        float adh = ad[h];
        for (int j = 0; j < deg; j++) {
            int s = g_se[beg + j].x;
            float e = __expf(leaky(g_as[s * 4 + h] + adh));
            uint4 raw = *(const uint4*)(g_gh + ((size_t)s << 8) + c8);
            float2 g0 = __half22float2(*(__half2*)&raw.x);
            float2 g1 = __half22float2(*(__half2*)&raw.y);
            float2 g2 = __half22float2(*(__half2*)&raw.z);
            float2 g3 = __half22float2(*(__half2*)&raw.w);
            a0 += e * g0.x; a1 += e * g0.y;
            a2 += e * g1.x; a3 += e * g1.y;
            a4 += e * g2.x; a5 += e * g2.y;
            a6 += e * g3.x; a7 += e * g3.y;
        }
    }
    float4 b0 = *(const float4*)(gbias + c8);
    float4 b1 = *(const float4*)(gbias + c8 + 4);
    float* outp = g_outg + (size_t)n * CDIM + c8;
    *(float4*)outp = make_float4(
        fmaxf(a0 * inv + b0.x, 0.f), fmaxf(a1 * inv + b0.y, 0.f),
        fmaxf(a2 * inv + b0.z, 0.f), fmaxf(a3 * inv + b0.w, 0.f));
    *(float4*)(outp + 4) = make_float4(
        fmaxf(a4 * inv + b1.x, 0.f), fmaxf(a5 * inv + b1.y, 0.f),
        fmaxf(a6 * inv + b1.z, 0.f), fmaxf(a7 * inv + b1.w, 0.f));
}

// ---------------- final linear via f32x2 (k-step-2) ----------------
__global__ void k_fc(const float* __restrict__ w, const float* __restrict__ b,
                     float* __restrict__ out) {
    __shared__ float sxP[16 * 512];
    int tid = threadIdx.x;
    int n0 = blockIdx.x * 32;
    for (int i = tid; i < 2048; i += 128) {
        int m0 = i >> 7, kq = i & 127;
        int na = n0 + m0, nb = na + 16;
        float2 a = (na < NN) ? *(const float2*)(g_outg + (size_t)na * 256 + kq * 2)
                             : make_float2(0.f, 0.f);
        float2 c = (nb < NN) ? *(const float2*)(g_outg + (size_t)nb * 256 + kq * 2)
                             : make_float2(0.f, 0.f);
        *(float4*)(sxP + m0 * 512 + kq * 4) = make_float4(a.x, c.x, a.y, c.y);
    }
    __syncthreads();
    int o = tid;
    unsigned long long acc[16];
#pragma unroll
    for (int m = 0; m < 16; m++) acc[m] = 0ULL;
#pragma unroll 2
    for (int k = 0; k < 256; k += 2) {
        float w0 = w[k * 128 + o];
        float w1 = w[(k + 1) * 128 + o];
        unsigned long long wd0 = pack2(w0, w0);
        unsigned long long wd1 = pack2(w1, w1);
#pragma unroll
        for (int m = 0; m < 16; m++) {
            ulonglong2 xv = *(const ulonglong2*)(sxP + m * 512 + k * 2);
            fma2(acc[m], xv.x, wd0);
            fma2(acc[m], xv.y, wd1);
        }
    }
    float bias = b[o];
#pragma unroll
    for (int m = 0; m < 16; m++) {
        float2 r = unpack2(acc[m]);
        int na = n0 + m, nb = na + 16;
        if (na < NN) out[(size_t)na * 128 + o] = r.x + bias;
        if (nb < NN) out[(size_t)nb * 128 + o] = r.y + bias;
    }
}

// ---------------- launcher ----------------
extern "C" void kernel_launch(void* const* d_in, const int* in_sizes, int n_in,
                              void* d_out, int out_size) {
    const float* x        = (const float*)d_in[0];
    const int*   ei       = (const int*)d_in[1];
    const float* ea       = (const float*)d_in[2];
    const float* ecc_root = (const float*)d_in[3];
    const float* ecc_bias = (const float*)d_in[4];
    const float* mlp_w    = (const float*)d_in[5];
    const float* mlp_b    = (const float*)d_in[6];
    const float* gat_lin  = (const float*)d_in[7];
    const float* att_src  = (const float*)d_in[8];
    const float* att_dst  = (const float*)d_in[9];
    const float* gat_bias = (const float*)d_in[10];
    const float* fc_w     = (const float*)d_in[11];
    const float* fc_b     = (const float*)d_in[12];
    float*       out      = (float*)d_out;

    k_hist<<<(NE / 4 + 255) / 256, 256>>>(ei);              // 0
    k_scanA<<<13, 256>>>();                                 // 1
    k_scatter<<<(NE / 4 + 255) / 256, 256>>>(ei);           // 2
    k_g<<<(NN + 15) / 16, 256>>>(x, ea, ecc_root, ecc_bias, gat_lin,
                                 att_src, att_dst, mlp_w, mlp_b); // 3 <- profiled
    k_gatagg<<<(NN + NPB - 1) / NPB, 256>>>(gat_bias);      // 4
    k_fc<<<(NN + 31) / 32, 128>>>(fc_w, fc_b, out);         // 5
}